// round 5
// baseline (speedup 1.0000x reference)
#include <cuda_runtime.h>
#include <stdint.h>

#define NB   16
#define KMAX 50
#define NG   76
#define GG   (NG*NG)      // 5776
#define NA   3
#define NCLS 80
#define NCH  85
#define CELLS (NA*GG)     // 17328
#define CPT  2
#define BLK  256
#define CPB  (BLK*CPT)    // 512
#define GROUPS (CELLS/CPT)            // 8664
#define NBLK ((GROUPS + BLK - 1)/BLK) // 34
#define TOTB (NB*NBLK)                // 544

__device__ double g_partial[TOTB];
__device__ int    g_count;

// softplus(x) = log(1+exp(x));  bce(sigmoid(x), t) = softplus(x) - t*x
__device__ __forceinline__ float splus(float x) {
    return __logf(1.0f + __expf(x));
}
__device__ __forceinline__ float sigm(float x) {
    return __fdividef(1.0f, 1.0f + __expf(-x));
}

__global__ void __launch_bounds__(BLK)
fused_kernel(const float* __restrict__ raw,
             const float* __restrict__ labels,
             const float* __restrict__ anchors_all,
             const int*   __restrict__ aidx,
             const int*   __restrict__ imgp,
             float*       __restrict__ out) {
    __shared__ float4   s_box[KMAX];
    __shared__ float    s_thr[KMAX];     // 0.375*area_g
    __shared__ int      s_cell[KMAX];
    __shared__ float    s_t[KMAX][5];    // t0..t3, w2
    __shared__ int      s_cls[KMAX];
    __shared__ float    s_awn[NA], s_ahn[NA];
    __shared__ unsigned s_bits[CPB/32];  // 16 words
    __shared__ int      s_cnt;
    __shared__ double   s_wsum[BLK/32];
    __shared__ int      s_last;

    const int b = blockIdx.y;
    const int t = threadIdx.x;
    const int lane = t & 31, wid = t >> 5;

    // ---------------- prep ---------------------------------------------------
    if (t == 0) s_cnt = 0;
    if (t < CPB/32) s_bits[t] = 0u;
    float img = (float)(*imgp);
    if (t < NA) {
        int ai = aidx[t];
        s_awn[t] = __fdividef(anchors_all[2*ai],     img);
        s_ahn[t] = __fdividef(anchors_all[2*ai + 1], img);
    }
    float lab[5];
    if (t < KMAX) {
        float s = 0.f;
        #pragma unroll
        for (int j = 0; j < 5; j++) { lab[j] = labels[(b*KMAX + t)*5 + j]; s += lab[j]; }
        if (s > 0.f) atomicAdd(&s_cnt, 1);
    }
    __syncthreads();
    const int nlabel = s_cnt;

    if (t < KMAX) {
        bool valid_k = (t < nlabel);
        float tx = lab[1] * (float)NG, ty = lab[2] * (float)NG;
        float tw = lab[3],             th = lab[4];

        int best_all = 0; float best = -1.0f;
        #pragma unroll
        for (int a = 0; a < 9; a++) {
            float aw = __fdividef(anchors_all[2*a], img);
            float ah = __fdividef(anchors_all[2*a+1], img);
            float inter = fminf(tw, aw) * fminf(th, ah);
            float uni   = tw*th + aw*ah - inter;
            float iou   = __fdividef(inter, fmaxf(uni, 1e-16f));
            if (iou > best) { best = iou; best_all = a; }
        }
        bool va = false;
        #pragma unroll
        for (int j = 0; j < NA; j++) va = va || (best_all == aidx[j]);
        int  best_n = best_all % NA;
        int  ti = (int)tx, tj = (int)ty;
        bool valid = valid_k && va && ti >= 0 && ti < NG && tj >= 0 && tj < NG;

        int   cell = -1;
        float t0=0.f,t1=0.f,t2=0.f,t3=0.f,w2=0.f;
        if (valid) {
            cell = (best_n * NG + tj) * NG + ti;
            t0 = tx - floorf(tx);
            t1 = ty - floorf(ty);
            t2 = __logf(__fdividef(tw, s_awn[best_n]) + 1e-16f);
            t3 = __logf(__fdividef(th, s_ahn[best_n]) + 1e-16f);
            w2 = 2.0f - tw * th;
            int local = cell - blockIdx.x * CPB;
            if (local >= 0 && local < CPB)
                atomicOr(&s_bits[local >> 5], 1u << (local & 31));
        }
        float gx=0.f,gy=0.f,gw=0.f,gh=0.f;
        if (valid_k) { gx = tx * (1.0f/(float)NG); gy = ty * (1.0f/(float)NG); gw = tw; gh = th; }

        s_box[t]  = make_float4(gx - gw*0.5f, gy - gh*0.5f, gx + gw*0.5f, gy + gh*0.5f);
        s_thr[t]  = 0.375f * gw * gh;
        s_cell[t] = cell;
        s_t[t][0]=t0; s_t[t][1]=t1; s_t[t][2]=t2; s_t[t][3]=t3; s_t[t][4]=w2;
        s_cls[t]  = (int)lab[0];
    }
    __syncthreads();

    double d = 0.0;

    // ---------------- warp-cooperative obj losses (xy, wh, classes) ---------
    {
        unsigned w0 = s_bits[wid*2], w1 = s_bits[wid*2 + 1];
        unsigned long long m = (unsigned long long)w0 | ((unsigned long long)w1 << 32);
        while (m) {
            int bit = __ffsll((long long)m) - 1;
            m &= m - 1ull;
            int cellg = blockIdx.x * CPB + wid * 64 + bit;
            int a  = cellg / GG;
            int r  = cellg - a * GG;
            int gy = r / NG, gx = r - gy * NG;

            // winner + per-lane class-target bits (scan shared, broadcast LDS)
            int winner = 0;
            int b0 = 0, b1 = 0, b2 = 0;
            for (int k = 0; k < nlabel; k++) {
                if (s_cell[k] == cellg) {
                    winner = k;                       // last writer wins
                    int cc = s_cls[k];
                    b0 |= (cc == lane);
                    b1 |= (cc == lane + 32);
                    b2 |= (cc == lane + 64);
                }
            }

            const float* base = raw + ((size_t)((b*NA + a)*NCH))*GG + gy*NG + gx;

            // classes: lane L handles L, L+32, (L+64 if L<16)
            float x0 = base[(5 + lane)      * GG];
            float x1 = base[(5 + lane + 32) * GG];
            float x2 = (lane < 16) ? base[(5 + lane + 64) * GG] : 0.0f;
            float cls_sum = (splus(x0) - (float)b0 * x0)
                          + (splus(x1) - (float)b1 * x1);
            if (lane < 16) cls_sum += splus(x2) - (float)b2 * x2;
            // warp reduce (fixed order)
            #pragma unroll
            for (int o = 16; o > 0; o >>= 1)
                cls_sum += __shfl_xor_sync(0xffffffffu, cls_sum, o);

            if (lane == 0) {
                float rx = base[0];
                float ry = base[1*GG];
                float rw = base[2*GG];
                float rh = base[3*GG];
                float t0 = s_t[winner][0], t1 = s_t[winner][1];
                float t2 = s_t[winner][2], t3 = s_t[winner][3];
                float w2 = s_t[winner][4];
                float lxy = (splus(rx) - t0*rx) + (splus(ry) - t1*ry);
                float dw = rw - t2, dh = rh - t3;
                d += (double)(cls_sum + w2 * (lxy + 0.5f*(dw*dw + dh*dh)));
            }
        }
    }

    // ---------------- main: ignore screen + conf loss ------------------------
    const int gidx = blockIdx.x * BLK + t;
    if (gidx < GROUPS) {
        const int cell0 = gidx * CPT;
        const int a  = cell0 / GG;
        const int r  = cell0 - a * GG;
        const int gy = r / NG, gx0 = r - gy * NG;   // even

        const float* base = raw + ((size_t)((b*NA + a)*NCH))*GG + gy*NG + gx0;
        float2 vx = *(const float2*)(base + 0*GG);
        float2 vy = *(const float2*)(base + 1*GG);
        float2 vw = *(const float2*)(base + 2*GG);
        float2 vh = *(const float2*)(base + 3*GG);
        float2 vc = *(const float2*)(base + 4*GG);

        float RX[CPT] = {vx.x, vx.y};
        float RY[CPT] = {vy.x, vy.y};
        float RW[CPT] = {vw.x, vw.y};
        float RH[CPT] = {vh.x, vh.y};
        float RC[CPT] = {vc.x, vc.y};

        float X1[CPT], Y1[CPT], X2[CPT], Y2[CPT], AP[CPT], MD[CPT];
        const float awn = s_awn[a], ahn = s_ahn[a];
        const float inv = 1.0f / (float)NG;
        #pragma unroll
        for (int c = 0; c < CPT; c++) {
            float px = (sigm(RX[c]) + (float)(gx0 + c)) * inv;
            float py = (sigm(RY[c]) + (float)gy) * inv;
            float pw = fminf(__expf(RW[c]) * awn, 1.0f);
            float ph = fminf(__expf(RH[c]) * ahn, 1.0f);
            X1[c] = px - pw*0.5f; Y1[c] = py - ph*0.5f;
            X2[c] = px + pw*0.5f; Y2[c] = py + ph*0.5f;
            AP[c] = 0.375f * pw * ph;
            MD[c] = -1e30f;
        }

        #pragma unroll 4
        for (int k = 0; k < nlabel; k++) {
            const float4 gb = s_box[k];
            const float  th = s_thr[k];
            #pragma unroll
            for (int c = 0; c < CPT; c++) {
                float iw = fminf(X2[c], gb.z) - fmaxf(X1[c], gb.x);
                float ih = fminf(Y2[c], gb.w) - fmaxf(Y1[c], gb.y);
                float inter = fmaxf(iw, 0.f) * fmaxf(ih, 0.f);
                MD[c] = fmaxf(MD[c], inter - th);
            }
        }

        #pragma unroll
        for (int c = 0; c < CPT; c++) {
            bool ign = MD[c] > AP[c];
            int  local = t * CPT + c;
            bool obj = (s_bits[local >> 5] >> (local & 31)) & 1u;
            // bce(conf, obj) = softplus(rc) - obj*rc  (clamp never active: |rc|<16)
            if ((!ign) || obj)
                d += (double)(splus(RC[c]) - (obj ? RC[c] : 0.0f));
        }
    }

    // ---------------- block reduction (deterministic) ------------------------
    #pragma unroll
    for (int o = 16; o > 0; o >>= 1) d += __shfl_down_sync(0xffffffffu, d, o);
    if (lane == 0) s_wsum[wid] = d;
    __syncthreads();
    if (t == 0) {
        double s = 0.0;
        #pragma unroll
        for (int w = 0; w < BLK/32; w++) s += s_wsum[w];
        g_partial[blockIdx.y * gridDim.x + blockIdx.x] = s;
        __threadfence();
        int c = atomicAdd(&g_count, 1);
        s_last = (c == TOTB - 1);
    }
    __syncthreads();

    // ---------------- last block: final reduction ----------------------------
    if (s_last) {
        __shared__ double sh[BLK];
        double s = 0.0;
        for (int i = t; i < TOTB; i += BLK) s += g_partial[i];
        sh[t] = s;
        __syncthreads();
        for (int o = BLK/2; o > 0; o >>= 1) {
            if (t < o) sh[t] += sh[t + o];
            __syncthreads();
        }
        if (t == 0) { out[0] = (float)sh[0]; g_count = 0; }
    }
}

extern "C" void kernel_launch(void* const* d_in, const int* in_sizes, int n_in,
                              void* d_out, int out_size) {
    const float* raw     = (const float*)d_in[0];
    const float* labels  = (const float*)d_in[1];
    const float* anchors = (const float*)d_in[2];
    const int*   aidx    = (const int*)d_in[3];
    const int*   imgp    = (const int*)d_in[4];

    dim3 grid(NBLK, NB);
    fused_kernel<<<grid, BLK>>>(raw, labels, anchors, aidx, imgp, (float*)d_out);
}